// round 3
// baseline (speedup 1.0000x reference)
#include <cuda_runtime.h>

#define NN 50000
#define NE 1600000
#define FH 240
#define FO 80

// ---------------- device scratch (no allocations allowed) ----------------
__device__ float g_dis[NN];                 // deg accumulator, then 1/sqrt(deg)
__device__ int   g_cnt[NN];                 // in-degree counts (edges only)
__device__ int   g_ptr[NN + 1];             // CSR row pointers (by target col)
__device__ int   g_cur[NN];                 // scatter cursors
__device__ int   g_rows[NE];                // source node per sorted edge
__device__ float g_norm[NE];                // norm per sorted edge
__device__ float g_h[(size_t)NN * FH];      // linear-transform output
__device__ float g_agg[(size_t)NN * FH];    // aggregated (post-relu) output

// ---------------- normalization + CSR build ----------------
__global__ void k_init() {
    int i = blockIdx.x * blockDim.x + threadIdx.x;
    if (i < NN) { g_dis[i] = 1.0f; g_cnt[i] = 0; }   // 1.0 = self-loop weight
}

__global__ void k_accum(const int* __restrict__ ei, const float* __restrict__ ew) {
    int e = blockIdx.x * blockDim.x + threadIdx.x;
    if (e < NE) {
        int c = ei[NE + e];                          // col (target)
        atomicAdd(&g_dis[c], ew[e]);
        atomicAdd(&g_cnt[c], 1);
    }
}

__global__ void k_rsqrt() {
    int i = blockIdx.x * blockDim.x + threadIdx.x;
    if (i < NN) g_dis[i] = rsqrtf(g_dis[i]);         // deg >= 1 always (self-loop)
}

// single-block exclusive scan of g_cnt -> g_ptr / g_cur
__global__ void k_scan() {
    __shared__ int warp_tot[32];
    __shared__ int s_carry;
    int tid = threadIdx.x, lane = tid & 31, wid = tid >> 5;
    if (tid == 0) s_carry = 0;
    __syncthreads();
    for (int base = 0; base < NN; base += 1024) {
        int idx = base + tid;
        int v = (idx < NN) ? g_cnt[idx] : 0;
        int incl = v;
        #pragma unroll
        for (int off = 1; off < 32; off <<= 1) {
            int n = __shfl_up_sync(0xffffffff, incl, off);
            if (lane >= off) incl += n;
        }
        if (lane == 31) warp_tot[wid] = incl;
        __syncthreads();
        if (wid == 0) {
            int wv = warp_tot[lane];
            int wi = wv;
            #pragma unroll
            for (int off = 1; off < 32; off <<= 1) {
                int n = __shfl_up_sync(0xffffffff, wi, off);
                if (lane >= off) wi += n;
            }
            warp_tot[lane] = wi - wv;                // exclusive warp offsets
        }
        __syncthreads();
        int excl = s_carry + warp_tot[wid] + incl - v;
        if (idx < NN) { g_ptr[idx] = excl; g_cur[idx] = excl; }
        __syncthreads();                             // all reads of s_carry done
        if (tid == 1023) s_carry = excl + v;
        __syncthreads();
    }
    if (tid == 0) g_ptr[NN] = s_carry;
}

__global__ void k_scatter(const int* __restrict__ ei, const float* __restrict__ ew) {
    int e = blockIdx.x * blockDim.x + threadIdx.x;
    if (e < NE) {
        int r = ei[e];
        int c = ei[NE + e];
        float nrm = g_dis[r] * ew[e] * g_dis[c];
        int pos = atomicAdd(&g_cur[c], 1);
        g_rows[pos] = r;
        g_norm[pos] = nrm;
    }
}

// ---------------- GEMM: C[N,M] = A[N,K] @ W[K,M] (+bias) ----------------
template <int ROWS, int COLS, int K, int M>
__global__ void k_gemm(const float* __restrict__ A, const float* __restrict__ W,
                       const float* __restrict__ bias, float* __restrict__ C) {
    __shared__ float As[ROWS * K];
    const int MC = M / COLS;
    int f = threadIdx.x;
    int base = blockIdx.x * ROWS;
    for (int idx = f; idx < ROWS * K; idx += MC)
        As[idx] = A[(size_t)base * K + idx];
    __syncthreads();

    float acc[ROWS][COLS];
    #pragma unroll
    for (int r = 0; r < ROWS; r++)
        #pragma unroll
        for (int c = 0; c < COLS; c++) acc[r][c] = 0.0f;

    #pragma unroll 4
    for (int k = 0; k < K; k++) {
        float w[COLS];
        #pragma unroll
        for (int c = 0; c < COLS; c++) w[c] = W[k * M + f + c * MC];
        #pragma unroll
        for (int r = 0; r < ROWS; r++) {
            float a = As[r * K + k];
            #pragma unroll
            for (int c = 0; c < COLS; c++) acc[r][c] = fmaf(a, w[c], acc[r][c]);
        }
    }

    #pragma unroll
    for (int c = 0; c < COLS; c++) {
        float bv = bias ? bias[f + c * MC] : 0.0f;
        #pragma unroll
        for (int r = 0; r < ROWS; r++)
            C[(size_t)(base + r) * M + f + c * MC] = acc[r][c] + bv;
    }
}

// ---------------- max aggregation + bias + relu, float4 gather -----------
// 256 threads / block, 4 nodes / block: 64 threads per node (60 active),
// each active thread owns 4 contiguous features -> LDG.128 gathers.
__global__ void k_agg(const float* __restrict__ h, const float* __restrict__ bias,
                      float* __restrict__ out) {
    int node = blockIdx.x * 4 + (threadIdx.x >> 6);
    int t4 = threadIdx.x & 63;                 // feature quad id
    if (t4 >= FH / 4 || node >= NN) return;
    int fbase = t4 * 4;

    float dii = g_dis[node];
    float sw = dii * dii;                      // self-loop norm (ew = 1)
    float4 hv = *(const float4*)&h[(size_t)node * FH + fbase];
    float m0 = sw * hv.x, m1 = sw * hv.y, m2 = sw * hv.z, m3 = sw * hv.w;

    int s = g_ptr[node], e = g_ptr[node + 1];
    #pragma unroll 4
    for (int j = s; j < e; j++) {
        int   r  = g_rows[j];
        float nw = g_norm[j];
        float4 v = *(const float4*)&h[(size_t)r * FH + fbase];
        m0 = fmaxf(m0, nw * v.x);
        m1 = fmaxf(m1, nw * v.y);
        m2 = fmaxf(m2, nw * v.z);
        m3 = fmaxf(m3, nw * v.w);
    }

    float4 bv = *(const float4*)&bias[fbase];
    float4 o;
    o.x = fmaxf(m0 + bv.x, 0.0f);
    o.y = fmaxf(m1 + bv.y, 0.0f);
    o.z = fmaxf(m2 + bv.z, 0.0f);
    o.w = fmaxf(m3 + bv.w, 0.0f);
    *(float4*)&out[(size_t)node * FH + fbase] = o;
}

// ---------------- launch ----------------
extern "C" void kernel_launch(void* const* d_in, const int* in_sizes, int n_in,
                              void* d_out, int out_size) {
    const float* x  = (const float*)d_in[0];
    const int*   ei = (const int*)d_in[1];
    const float* ew = (const float*)d_in[2];
    const float* W1 = (const float*)d_in[3];
    const float* b1 = (const float*)d_in[4];
    const float* W2 = (const float*)d_in[5];
    const float* b2 = (const float*)d_in[6];
    const float* We = (const float*)d_in[7];
    const float* be = (const float*)d_in[8];
    float*       out = (float*)d_out;

    float* hbuf;  cudaGetSymbolAddress((void**)&hbuf,  g_h);
    float* abuf;  cudaGetSymbolAddress((void**)&abuf,  g_agg);

    k_init  <<<(NN + 255) / 256, 256>>>();
    k_accum <<<(NE + 255) / 256, 256>>>(ei, ew);
    k_rsqrt <<<(NN + 255) / 256, 256>>>();
    k_scan  <<<1, 1024>>>();
    k_scatter<<<(NE + 255) / 256, 256>>>(ei, ew);

    // layer 1: x[N,5] @ W1[5,240] -> h; max-agg + b1 + relu -> agg
    k_gemm<16, 2, 5, FH><<<NN / 16, FH / 2>>>(x, W1, nullptr, hbuf);
    k_agg<<<(NN + 3) / 4, 256>>>(hbuf, b1, abuf);

    // layer 2: agg @ W2[240,240] -> h; max-agg + b2 + relu -> agg
    k_gemm<16, 2, FH, FH><<<NN / 16, FH / 2>>>(abuf, W2, nullptr, hbuf);
    k_agg<<<(NN + 3) / 4, 256>>>(hbuf, b2, abuf);

    // head: agg @ We[240,80] + be -> out
    k_gemm<16, 1, FH, FO><<<NN / 16, FO>>>(abuf, We, be, out);
}

// round 4
// speedup vs baseline: 1.1908x; 1.1908x over previous
#include <cuda_runtime.h>
#include <cstdint>

#define NN 50000
#define NE 1600000
#define FH 240
#define FO 80
#define SCAN_B 256
#define SCAN_NB ((NN + SCAN_B - 1) / SCAN_B)   // 196

// ---------------- device scratch (no allocations allowed) ----------------
__device__ float g_dis[NN];                 // deg accumulator, then 1/sqrt(deg)
__device__ int   g_cnt[NN];                 // in-degree counts (edges only)
__device__ int   g_ptr[NN + 1];             // CSR row pointers (by target col)
__device__ int   g_cur[NN];                 // scatter cursors
__device__ int   g_blk[SCAN_NB];            // per-block scan totals
__device__ int   g_blkoff[SCAN_NB];         // per-block scan offsets
__device__ int   g_rows[NE];                // source node per sorted edge
__device__ float g_norm[NE];                // norm per sorted edge
__device__ float g_h[(size_t)NN * FH];      // linear-transform output
__device__ float g_agg[(size_t)NN * FH];    // aggregated (post-relu) output

// ---------------- normalization + CSR build ----------------
__global__ void k_init() {
    int i = blockIdx.x * blockDim.x + threadIdx.x;
    if (i < NN) { g_dis[i] = 1.0f; g_cnt[i] = 0; }   // 1.0 = self-loop weight
}

__global__ void k_accum(const int* __restrict__ ei, const float* __restrict__ ew) {
    int e = blockIdx.x * blockDim.x + threadIdx.x;
    if (e < NE) {
        int c = ei[NE + e];                          // col (target)
        atomicAdd(&g_dis[c], ew[e]);
        atomicAdd(&g_cnt[c], 1);
    }
}

__global__ void k_rsqrt() {
    int i = blockIdx.x * blockDim.x + threadIdx.x;
    if (i < NN) g_dis[i] = rsqrtf(g_dis[i]);         // deg >= 1 always (self-loop)
}

// ---- 3-phase scan: per-block local exclusive scan -> scan block sums -> add
__device__ __forceinline__ int warp_incl_scan(int v, int lane) {
    #pragma unroll
    for (int off = 1; off < 32; off <<= 1) {
        int n = __shfl_up_sync(0xffffffff, v, off);
        if (lane >= off) v += n;
    }
    return v;
}

__global__ void k_scan1() {
    __shared__ int wsum[8];
    int b = blockIdx.x, tid = threadIdx.x, lane = tid & 31, w = tid >> 5;
    int idx = b * SCAN_B + tid;
    int v = (idx < NN) ? g_cnt[idx] : 0;
    int incl = warp_incl_scan(v, lane);
    if (lane == 31) wsum[w] = incl;
    __syncthreads();
    if (w == 0) {
        int t = (lane < 8) ? wsum[lane] : 0;
        int ts = warp_incl_scan(t, lane);
        if (lane < 8) wsum[lane] = ts - t;           // exclusive warp offsets
    }
    __syncthreads();
    int excl = wsum[w] + incl - v;
    if (idx < NN) g_ptr[idx] = excl;                 // block-local exclusive
    if (tid == SCAN_B - 1) g_blk[b] = excl + v;      // block total
}

__global__ void k_scan2() {                          // 1 block, 256 threads
    __shared__ int wsum[8];
    int tid = threadIdx.x, lane = tid & 31, w = tid >> 5;
    int v = (tid < SCAN_NB) ? g_blk[tid] : 0;
    int incl = warp_incl_scan(v, lane);
    if (lane == 31) wsum[w] = incl;
    __syncthreads();
    if (w == 0) {
        int t = (lane < 8) ? wsum[lane] : 0;
        int ts = warp_incl_scan(t, lane);
        if (lane < 8) wsum[lane] = ts - t;
    }
    __syncthreads();
    if (tid < SCAN_NB) g_blkoff[tid] = wsum[w] + incl - v;
    if (tid == 0) g_ptr[NN] = NE;                    // total is statically NE
}

__global__ void k_scan3() {
    int idx = blockIdx.x * SCAN_B + threadIdx.x;
    if (idx < NN) {
        int p = g_ptr[idx] + g_blkoff[blockIdx.x];
        g_ptr[idx] = p;
        g_cur[idx] = p;
    }
}

__global__ void k_scatter(const int* __restrict__ ei, const float* __restrict__ ew) {
    int e = blockIdx.x * blockDim.x + threadIdx.x;
    if (e < NE) {
        int r = ei[e];
        int c = ei[NE + e];
        float nrm = g_dis[r] * ew[e] * g_dis[c];
        int pos = atomicAdd(&g_cur[c], 1);
        g_rows[pos] = r;
        g_norm[pos] = nrm;
    }
}

// ---------------- GEMM1: x[N,5] @ W1[5,240] (memory-bound, trivial K) ----
__global__ void k_gemm1(const float* __restrict__ A, const float* __restrict__ W,
                        float* __restrict__ C) {
    int idx = blockIdx.x * blockDim.x + threadIdx.x;
    if (idx >= NN * FH) return;
    int n = idx / FH, m = idx - n * FH;
    const float* a = A + n * 5;
    float s = a[0] * W[0 * FH + m];
    s = fmaf(a[1], W[1 * FH + m], s);
    s = fmaf(a[2], W[2 * FH + m], s);
    s = fmaf(a[3], W[3 * FH + m], s);
    s = fmaf(a[4], W[4 * FH + m], s);
    C[idx] = s;
}

// ---------------- packed-f32x2 GEMM: C[N,M] = A[N,240] @ W[240,M] --------
// 16 rows per block, row-pairs (r, r+8) packed in smem so the A operand of
// fma.rn.f32x2 is one broadcast LDS.64; W splat-packed once per k per col.
#define FMA2(d, a, b, c) \
    asm("fma.rn.f32x2 %0, %1, %2, %3;" : "=l"(d) : "l"(a), "l"(b), "l"(c))

template <int M, int COLS>
__global__ void k_gemm_p(const float* __restrict__ A, const float* __restrict__ W,
                         const float* __restrict__ bias, float* __restrict__ C) {
    const int MC = M / COLS;
    __shared__ float As[FH * 16];    // [k*16 + rp*2 + hi]: pair (r=rp, r=rp+8)
    int f = threadIdx.x;
    int base = blockIdx.x * 16;
    for (int idx = f; idx < 16 * FH; idx += blockDim.x) {
        int r = idx / FH, k = idx - r * FH;
        As[k * 16 + (r & 7) * 2 + (r >> 3)] = A[(size_t)(base + r) * FH + k];
    }
    __syncthreads();
    if (f >= MC) return;

    unsigned long long acc[8][COLS];
    #pragma unroll
    for (int rp = 0; rp < 8; rp++)
        #pragma unroll
        for (int c = 0; c < COLS; c++) acc[rp][c] = 0ull;

    const unsigned long long* As2 = (const unsigned long long*)As;
    #pragma unroll 4
    for (int k = 0; k < FH; k++) {
        unsigned long long w2[COLS];
        #pragma unroll
        for (int c = 0; c < COLS; c++) {
            unsigned int wu = __float_as_uint(W[k * M + f + c * MC]);
            asm("mov.b64 %0, {%1, %1};" : "=l"(w2[c]) : "r"(wu));
        }
        #pragma unroll
        for (int rp = 0; rp < 8; rp++) {
            unsigned long long a2 = As2[k * 8 + rp];
            #pragma unroll
            for (int c = 0; c < COLS; c++)
                FMA2(acc[rp][c], a2, w2[c], acc[rp][c]);
        }
    }

    #pragma unroll
    for (int c = 0; c < COLS; c++) {
        float bv = bias ? bias[f + c * MC] : 0.0f;
        #pragma unroll
        for (int rp = 0; rp < 8; rp++) {
            unsigned int lo, hi;
            asm("mov.b64 {%0, %1}, %2;" : "=r"(lo), "=r"(hi) : "l"(acc[rp][c]));
            C[(size_t)(base + rp) * M + f + c * MC]     = __uint_as_float(lo) + bv;
            C[(size_t)(base + rp + 8) * M + f + c * MC] = __uint_as_float(hi) + bv;
        }
    }
}

// ---------------- max aggregation + bias + relu, float4 gather -----------
__global__ void k_agg(const float* __restrict__ h, const float* __restrict__ bias,
                      float* __restrict__ out) {
    int node = blockIdx.x * 4 + (threadIdx.x >> 6);
    int t4 = threadIdx.x & 63;                 // feature quad id
    if (t4 >= FH / 4 || node >= NN) return;
    int fbase = t4 * 4;

    float dii = g_dis[node];
    float sw = dii * dii;                      // self-loop norm (ew = 1)
    float4 hv = *(const float4*)&h[(size_t)node * FH + fbase];
    float m0 = sw * hv.x, m1 = sw * hv.y, m2 = sw * hv.z, m3 = sw * hv.w;

    int s = g_ptr[node], e = g_ptr[node + 1];
    #pragma unroll 4
    for (int j = s; j < e; j++) {
        int   r  = g_rows[j];
        float nw = g_norm[j];
        float4 v = *(const float4*)&h[(size_t)r * FH + fbase];
        m0 = fmaxf(m0, nw * v.x);
        m1 = fmaxf(m1, nw * v.y);
        m2 = fmaxf(m2, nw * v.z);
        m3 = fmaxf(m3, nw * v.w);
    }

    float4 bv = *(const float4*)&bias[fbase];
    float4 o;
    o.x = fmaxf(m0 + bv.x, 0.0f);
    o.y = fmaxf(m1 + bv.y, 0.0f);
    o.z = fmaxf(m2 + bv.z, 0.0f);
    o.w = fmaxf(m3 + bv.w, 0.0f);
    *(float4*)&out[(size_t)node * FH + fbase] = o;
}

// ---------------- launch ----------------
extern "C" void kernel_launch(void* const* d_in, const int* in_sizes, int n_in,
                              void* d_out, int out_size) {
    const float* x  = (const float*)d_in[0];
    const int*   ei = (const int*)d_in[1];
    const float* ew = (const float*)d_in[2];
    const float* W1 = (const float*)d_in[3];
    const float* b1 = (const float*)d_in[4];
    const float* W2 = (const float*)d_in[5];
    const float* b2 = (const float*)d_in[6];
    const float* We = (const float*)d_in[7];
    const float* be = (const float*)d_in[8];
    float*       out = (float*)d_out;

    float* hbuf;  cudaGetSymbolAddress((void**)&hbuf,  g_h);
    float* abuf;  cudaGetSymbolAddress((void**)&abuf,  g_agg);

    k_init  <<<(NN + 255) / 256, 256>>>();
    k_accum <<<(NE + 255) / 256, 256>>>(ei, ew);
    k_rsqrt <<<(NN + 255) / 256, 256>>>();
    k_scan1 <<<SCAN_NB, SCAN_B>>>();
    k_scan2 <<<1, 256>>>();
    k_scan3 <<<SCAN_NB, SCAN_B>>>();
    k_scatter<<<(NE + 255) / 256, 256>>>(ei, ew);

    // layer 1: x[N,5] @ W1[5,240] -> h; max-agg + b1 + relu -> agg
    k_gemm1<<<(NN * FH + 255) / 256, 256>>>(x, W1, hbuf);
    k_agg<<<(NN + 3) / 4, 256>>>(hbuf, b1, abuf);

    // layer 2: agg @ W2[240,240] -> h; max-agg + b2 + relu -> agg
    k_gemm_p<FH, 2><<<NN / 16, 128>>>(abuf, W2, nullptr, hbuf);
    k_agg<<<(NN + 3) / 4, 256>>>(hbuf, b2, abuf);

    // head: agg @ We[240,80] + be -> out
    k_gemm_p<FO, 1><<<NN / 16, 96>>>(abuf, We, be, out);
}

// round 5
// speedup vs baseline: 1.2241x; 1.0280x over previous
#include <cuda_runtime.h>
#include <cuda_fp16.h>
#include <cstdint>

#define NN 50000
#define NE 1600000
#define FH 240
#define FO 80
#define SCAN_B 256
#define SCAN_NB ((NN + SCAN_B - 1) / SCAN_B)   // 196

// ---------------- device scratch (no allocations allowed) ----------------
__device__ float g_dis[NN];                 // deg accumulator, then 1/sqrt(deg)
__device__ int   g_cnt[NN];                 // in-degree counts (edges only)
__device__ int   g_ptr[NN + 1];             // CSR row pointers (by target col)
__device__ int   g_cur[NN];                 // scatter cursors
__device__ int   g_blk[SCAN_NB];            // per-block scan totals
__device__ int   g_blkoff[SCAN_NB];         // per-block scan offsets
__device__ int   g_rows[NE];                // source node per sorted edge
__device__ float g_norm[NE];                // norm per sorted edge
__device__ float g_h[(size_t)NN * FH];      // linear-transform output (fp32)
__device__ uint2 g_h16[(size_t)NN * (FH/4)];// fp16 copy of h (4 halfs per uint2)
__device__ float g_agg[(size_t)NN * FH];    // aggregated (post-relu) output

// ---------------- normalization + CSR build ----------------
__global__ void k_init() {
    int i = blockIdx.x * blockDim.x + threadIdx.x;
    if (i < NN) { g_dis[i] = 1.0f; g_cnt[i] = 0; }   // 1.0 = self-loop weight
}

__global__ void k_accum(const int* __restrict__ ei, const float* __restrict__ ew) {
    int e = blockIdx.x * blockDim.x + threadIdx.x;
    if (e < NE) {
        int c = ei[NE + e];                          // col (target)
        atomicAdd(&g_dis[c], ew[e]);
        atomicAdd(&g_cnt[c], 1);
    }
}

__global__ void k_rsqrt() {
    int i = blockIdx.x * blockDim.x + threadIdx.x;
    if (i < NN) g_dis[i] = rsqrtf(g_dis[i]);         // deg >= 1 always (self-loop)
}

// ---- 3-phase scan ----
__device__ __forceinline__ int warp_incl_scan(int v, int lane) {
    #pragma unroll
    for (int off = 1; off < 32; off <<= 1) {
        int n = __shfl_up_sync(0xffffffff, v, off);
        if (lane >= off) v += n;
    }
    return v;
}

__global__ void k_scan1() {
    __shared__ int wsum[8];
    int b = blockIdx.x, tid = threadIdx.x, lane = tid & 31, w = tid >> 5;
    int idx = b * SCAN_B + tid;
    int v = (idx < NN) ? g_cnt[idx] : 0;
    int incl = warp_incl_scan(v, lane);
    if (lane == 31) wsum[w] = incl;
    __syncthreads();
    if (w == 0) {
        int t = (lane < 8) ? wsum[lane] : 0;
        int ts = warp_incl_scan(t, lane);
        if (lane < 8) wsum[lane] = ts - t;
    }
    __syncthreads();
    int excl = wsum[w] + incl - v;
    if (idx < NN) g_ptr[idx] = excl;
    if (tid == SCAN_B - 1) g_blk[b] = excl + v;
}

__global__ void k_scan2() {                          // 1 block, 256 threads
    __shared__ int wsum[8];
    int tid = threadIdx.x, lane = tid & 31, w = tid >> 5;
    int v = (tid < SCAN_NB) ? g_blk[tid] : 0;
    int incl = warp_incl_scan(v, lane);
    if (lane == 31) wsum[w] = incl;
    __syncthreads();
    if (w == 0) {
        int t = (lane < 8) ? wsum[lane] : 0;
        int ts = warp_incl_scan(t, lane);
        if (lane < 8) wsum[lane] = ts - t;
    }
    __syncthreads();
    if (tid < SCAN_NB) g_blkoff[tid] = wsum[w] + incl - v;
    if (tid == 0) g_ptr[NN] = NE;
}

__global__ void k_scan3() {
    int idx = blockIdx.x * SCAN_B + threadIdx.x;
    if (idx < NN) {
        int p = g_ptr[idx] + g_blkoff[blockIdx.x];
        g_ptr[idx] = p;
        g_cur[idx] = p;
    }
}

__global__ void k_scatter(const int* __restrict__ ei, const float* __restrict__ ew) {
    int e = blockIdx.x * blockDim.x + threadIdx.x;
    if (e < NE) {
        int r = ei[e];
        int c = ei[NE + e];
        float nrm = g_dis[r] * ew[e] * g_dis[c];
        int pos = atomicAdd(&g_cur[c], 1);
        g_rows[pos] = r;
        g_norm[pos] = nrm;
    }
}

// ---------------- GEMM1: x[N,5] @ W1[5,240] (memory-bound) ----------------
__global__ void k_gemm1(const float* __restrict__ A, const float* __restrict__ W,
                        float* __restrict__ C, __half* __restrict__ C16) {
    int idx = blockIdx.x * blockDim.x + threadIdx.x;
    if (idx >= NN * FH) return;
    int n = idx / FH, m = idx - n * FH;
    const float* a = A + n * 5;
    float s = a[0] * W[0 * FH + m];
    s = fmaf(a[1], W[1 * FH + m], s);
    s = fmaf(a[2], W[2 * FH + m], s);
    s = fmaf(a[3], W[3 * FH + m], s);
    s = fmaf(a[4], W[4 * FH + m], s);
    C[idx] = s;
    C16[idx] = __float2half(s);
}

// ---------------- packed-f32x2 GEMM: C[N,M] = A[N,240] @ W[240,M] --------
// 16 rows/block; row-pairs (r, r+8) packed in smem -> broadcast LDS.64 A.
// Thread f owns COLS adjacent columns (COLS*f ..) -> float2 W loads/stores.
#define FMA2(d, a, b, c) \
    asm("fma.rn.f32x2 %0, %1, %2, %3;" : "=l"(d) : "l"(a), "l"(b), "l"(c))

template <int M, int COLS, bool WRITE_H16>
__global__ void k_gemm_p(const float* __restrict__ A, const float* __restrict__ W,
                         const float* __restrict__ bias, float* __restrict__ C,
                         __half2* __restrict__ C16) {
    const int MC = M / COLS;                 // active threads
    __shared__ float As[FH * 16];            // [k*16 + rp*2 + hi]
    int f = threadIdx.x;
    int base = blockIdx.x * 16;
    for (int idx = f; idx < 16 * FH; idx += blockDim.x) {
        int r = idx / FH, k = idx - r * FH;
        As[k * 16 + (r & 7) * 2 + (r >> 3)] = A[(size_t)(base + r) * FH + k];
    }
    __syncthreads();
    if (f >= MC) return;

    unsigned long long acc[8][COLS];
    #pragma unroll
    for (int rp = 0; rp < 8; rp++)
        #pragma unroll
        for (int c = 0; c < COLS; c++) acc[rp][c] = 0ull;

    const unsigned long long* As2 = (const unsigned long long*)As;
    #pragma unroll 4
    for (int k = 0; k < FH; k++) {
        unsigned long long w2[COLS];
        if (COLS == 2) {
            float2 wv = *(const float2*)&W[k * M + 2 * f];
            asm("mov.b64 %0, {%1, %1};" : "=l"(w2[0]) : "r"(__float_as_uint(wv.x)));
            asm("mov.b64 %0, {%1, %1};" : "=l"(w2[1]) : "r"(__float_as_uint(wv.y)));
        } else {
            unsigned int wu = __float_as_uint(W[k * M + f]);
            asm("mov.b64 %0, {%1, %1};" : "=l"(w2[0]) : "r"(wu));
        }
        #pragma unroll
        for (int rp = 0; rp < 8; rp++) {
            unsigned long long a2 = As2[k * 8 + rp];
            #pragma unroll
            for (int c = 0; c < COLS; c++)
                FMA2(acc[rp][c], a2, w2[c], acc[rp][c]);
        }
    }

    #pragma unroll
    for (int rp = 0; rp < 8; rp++) {
        #pragma unroll
        for (int half = 0; half < 2; half++) {       // lo = row rp, hi = row rp+8
            int row = base + rp + half * 8;
            float v[COLS];
            #pragma unroll
            for (int c = 0; c < COLS; c++) {
                unsigned int lo, hi;
                asm("mov.b64 {%0, %1}, %2;" : "=r"(lo), "=r"(hi) : "l"(acc[rp][c]));
                unsigned int u = half ? hi : lo;
                float bv = bias ? bias[COLS * f + c] : 0.0f;
                v[c] = __uint_as_float(u) + bv;
            }
            if (COLS == 2) {
                *(float2*)&C[(size_t)row * M + 2 * f] = make_float2(v[0], v[1]);
                if (WRITE_H16)
                    C16[(size_t)row * (M / 2) + f] = __floats2half2_rn(v[0], v[1]);
            } else {
                C[(size_t)row * M + f] = v[0];
            }
        }
    }
}

// ---------------- max aggregation + bias + relu ---------------------------
// 4 nodes/block, 64 threads/node (60 active), each owns 4 features.
// Self term from fp32 h; neighbor gathers from fp16 copy (half traffic).
__global__ void k_agg(const float* __restrict__ h32, const uint2* __restrict__ h16,
                      const float* __restrict__ bias, float* __restrict__ out) {
    int node = blockIdx.x * 4 + (threadIdx.x >> 6);
    int t4 = threadIdx.x & 63;                 // feature quad id
    if (t4 >= FH / 4 || node >= NN) return;
    int fbase = t4 * 4;

    float dii = g_dis[node];
    float sw = dii * dii;                      // self-loop norm (ew = 1)
    float4 hv = *(const float4*)&h32[(size_t)node * FH + fbase];
    float m0 = sw * hv.x, m1 = sw * hv.y, m2 = sw * hv.z, m3 = sw * hv.w;

    int s = g_ptr[node], e = g_ptr[node + 1];
    #pragma unroll 4
    for (int j = s; j < e; j++) {
        int   r  = g_rows[j];
        float nw = g_norm[j];
        uint2 p = h16[(size_t)r * (FH / 4) + t4];
        float2 fa = __half22float2(*(const __half2*)&p.x);
        float2 fb = __half22float2(*(const __half2*)&p.y);
        m0 = fmaxf(m0, nw * fa.x);
        m1 = fmaxf(m1, nw * fa.y);
        m2 = fmaxf(m2, nw * fb.x);
        m3 = fmaxf(m3, nw * fb.y);
    }

    float4 bv = *(const float4*)&bias[fbase];
    float4 o;
    o.x = fmaxf(m0 + bv.x, 0.0f);
    o.y = fmaxf(m1 + bv.y, 0.0f);
    o.z = fmaxf(m2 + bv.z, 0.0f);
    o.w = fmaxf(m3 + bv.w, 0.0f);
    *(float4*)&out[(size_t)node * FH + fbase] = o;
}

// ---------------- launch ----------------
extern "C" void kernel_launch(void* const* d_in, const int* in_sizes, int n_in,
                              void* d_out, int out_size) {
    const float* x  = (const float*)d_in[0];
    const int*   ei = (const int*)d_in[1];
    const float* ew = (const float*)d_in[2];
    const float* W1 = (const float*)d_in[3];
    const float* b1 = (const float*)d_in[4];
    const float* W2 = (const float*)d_in[5];
    const float* b2 = (const float*)d_in[6];
    const float* We = (const float*)d_in[7];
    const float* be = (const float*)d_in[8];
    float*       out = (float*)d_out;

    float* hbuf;  cudaGetSymbolAddress((void**)&hbuf,  g_h);
    uint2* h16;   cudaGetSymbolAddress((void**)&h16,   g_h16);
    float* abuf;  cudaGetSymbolAddress((void**)&abuf,  g_agg);

    k_init  <<<(NN + 255) / 256, 256>>>();
    k_accum <<<(NE + 255) / 256, 256>>>(ei, ew);
    k_rsqrt <<<(NN + 255) / 256, 256>>>();
    k_scan1 <<<SCAN_NB, SCAN_B>>>();
    k_scan2 <<<1, 256>>>();
    k_scan3 <<<SCAN_NB, SCAN_B>>>();
    k_scatter<<<(NE + 255) / 256, 256>>>(ei, ew);

    // layer 1: x[N,5] @ W1[5,240] -> h (+fp16); max-agg + b1 + relu -> agg
    k_gemm1<<<(NN * FH + 255) / 256, 256>>>(x, W1, hbuf, (__half*)h16);
    k_agg<<<(NN + 3) / 4, 256>>>(hbuf, h16, b1, abuf);

    // layer 2: agg @ W2[240,240] -> h (+fp16); max-agg + b2 + relu -> agg
    k_gemm_p<FH, 2, true><<<NN / 16, 128>>>(abuf, W2, nullptr, hbuf, (__half2*)h16);
    k_agg<<<(NN + 3) / 4, 256>>>(hbuf, h16, b2, abuf);

    // head: agg @ We[240,80] + be -> out
    k_gemm_p<FO, 1, false><<<NN / 16, 96>>>(abuf, We, be, out, nullptr);
}